// round 4
// baseline (speedup 1.0000x reference)
#include <cuda_runtime.h>
#include <cuda_bf16.h>

// DotPredictor: out[e] = sigmoid(dot(h[src[e]], h[dst[e]])), D = 64 fp32.
// Indices are int32 (JAX x64 disabled).
// 4 lanes per edge; each lane loads 4 float4 from src row + 4 from dst row
// (MLP=8), 32 FMAs, 2-step shfl reduction. h (12.8 MB) is L2-resident.

#define D 64

__global__ void __launch_bounds__(256) dotpred_kernel(
    const float* __restrict__ h,
    const int* __restrict__ src,
    const int* __restrict__ dst,
    float* __restrict__ out,
    int E)
{
    int gid  = blockIdx.x * blockDim.x + threadIdx.x;
    int edge = gid >> 2;          // 4 lanes per edge
    int lane = gid & 3;
    if (edge >= E) return;

    int s = src[edge];
    int d = dst[edge];

    const float4* __restrict__ hs =
        reinterpret_cast<const float4*>(h + (long long)s * D);
    const float4* __restrict__ hd =
        reinterpret_cast<const float4*>(h + (long long)d * D);

    // 8 independent 16B loads in flight
    float4 a0 = hs[lane];
    float4 a1 = hs[lane + 4];
    float4 a2 = hs[lane + 8];
    float4 a3 = hs[lane + 12];
    float4 b0 = hd[lane];
    float4 b1 = hd[lane + 4];
    float4 b2 = hd[lane + 8];
    float4 b3 = hd[lane + 12];

    // Two independent accumulator chains for FMA ILP
    float acc0 = a0.x * b0.x;
    float acc1 = a1.x * b1.x;
    acc0 = fmaf(a0.y, b0.y, acc0);
    acc1 = fmaf(a1.y, b1.y, acc1);
    acc0 = fmaf(a0.z, b0.z, acc0);
    acc1 = fmaf(a1.z, b1.z, acc1);
    acc0 = fmaf(a0.w, b0.w, acc0);
    acc1 = fmaf(a1.w, b1.w, acc1);
    acc0 = fmaf(a2.x, b2.x, acc0);
    acc1 = fmaf(a3.x, b3.x, acc1);
    acc0 = fmaf(a2.y, b2.y, acc0);
    acc1 = fmaf(a3.y, b3.y, acc1);
    acc0 = fmaf(a2.z, b2.z, acc0);
    acc1 = fmaf(a3.z, b3.z, acc1);
    acc0 = fmaf(a2.w, b2.w, acc0);
    acc1 = fmaf(a3.w, b3.w, acc1);

    float acc = acc0 + acc1;

    // Reduce across the 4-lane group (xor pattern stays within group)
    acc += __shfl_xor_sync(0xFFFFFFFFu, acc, 2);
    acc += __shfl_xor_sync(0xFFFFFFFFu, acc, 1);

    if (lane == 0) {
        out[edge] = 1.0f / (1.0f + __expf(-acc));
    }
}

extern "C" void kernel_launch(void* const* d_in, const int* in_sizes, int n_in,
                              void* d_out, int out_size)
{
    const float* h   = (const float*)d_in[0];
    const int*   src = (const int*)d_in[1];
    const int*   dst = (const int*)d_in[2];
    float*       out = (float*)d_out;

    int E = in_sizes[1];  // number of edges

    long long total_threads = (long long)E * 4;
    int threads = 256;
    int blocks  = (int)((total_threads + threads - 1) / threads);

    dotpred_kernel<<<blocks, threads>>>(h, src, dst, out, E);
}

// round 5
// speedup vs baseline: 1.1842x; 1.1842x over previous
#include <cuda_runtime.h>
#include <cuda_bf16.h>

// DotPredictor: out[e] = sigmoid(dot(h[src[e]], h[dst[e]])), D = 64 fp32.
// Indices are int32 (JAX x64 disabled).
// 8 lanes per group, 2 edges per group: each lane issues 8 independent
// LDG.128s (MLP=8), every warp-level LDG covers full 128B lines
// (wavefront-optimal), 3-step shfl reduction per edge.
// h (12.8 MB) is L2-resident.

#define D 64

__global__ void __launch_bounds__(256) dotpred_kernel(
    const float* __restrict__ h,
    const int* __restrict__ src,
    const int* __restrict__ dst,
    float* __restrict__ out,
    int E)
{
    int gid   = blockIdx.x * blockDim.x + threadIdx.x;
    int group = gid >> 3;            // 8 lanes per group
    int lane  = gid & 7;
    int e0 = group * 2;
    int e1 = e0 + 1;
    if (e0 >= E) return;
    bool has_e1 = (e1 < E);

    // Vectorized index loads: edge pair is 8B-aligned in src/dst
    int2 ss = reinterpret_cast<const int2*>(src)[group];
    int2 dd = reinterpret_cast<const int2*>(dst)[group];

    const float4* __restrict__ s0p =
        reinterpret_cast<const float4*>(h + (long long)ss.x * D);
    const float4* __restrict__ d0p =
        reinterpret_cast<const float4*>(h + (long long)dd.x * D);
    const float4* __restrict__ s1p =
        reinterpret_cast<const float4*>(h + (long long)(has_e1 ? ss.y : ss.x) * D);
    const float4* __restrict__ d1p =
        reinterpret_cast<const float4*>(h + (long long)(has_e1 ? dd.y : dd.x) * D);

    // 8 independent 16B loads; each warp-level LDG covers 4 full 128B lines
    float4 a0 = s0p[lane];
    float4 a1 = s0p[lane + 8];
    float4 b0 = d0p[lane];
    float4 b1 = d0p[lane + 8];
    float4 c0 = s1p[lane];
    float4 c1 = s1p[lane + 8];
    float4 f0 = d1p[lane];
    float4 f1 = d1p[lane + 8];

    float acc0 = a0.x * b0.x;
    float acc1 = c0.x * f0.x;
    acc0 = fmaf(a0.y, b0.y, acc0);
    acc1 = fmaf(c0.y, f0.y, acc1);
    acc0 = fmaf(a0.z, b0.z, acc0);
    acc1 = fmaf(c0.z, f0.z, acc1);
    acc0 = fmaf(a0.w, b0.w, acc0);
    acc1 = fmaf(c0.w, f0.w, acc1);
    acc0 = fmaf(a1.x, b1.x, acc0);
    acc1 = fmaf(c1.x, f1.x, acc1);
    acc0 = fmaf(a1.y, b1.y, acc0);
    acc1 = fmaf(c1.y, f1.y, acc1);
    acc0 = fmaf(a1.z, b1.z, acc0);
    acc1 = fmaf(c1.z, f1.z, acc1);
    acc0 = fmaf(a1.w, b1.w, acc0);
    acc1 = fmaf(c1.w, f1.w, acc1);

    // Reduce both accumulators across the 8-lane group
    acc0 += __shfl_xor_sync(0xFFFFFFFFu, acc0, 4);
    acc1 += __shfl_xor_sync(0xFFFFFFFFu, acc1, 4);
    acc0 += __shfl_xor_sync(0xFFFFFFFFu, acc0, 2);
    acc1 += __shfl_xor_sync(0xFFFFFFFFu, acc1, 2);
    acc0 += __shfl_xor_sync(0xFFFFFFFFu, acc0, 1);
    acc1 += __shfl_xor_sync(0xFFFFFFFFu, acc1, 1);

    if (lane == 0) {
        out[e0] = 1.0f / (1.0f + __expf(-acc0));
        if (has_e1)
            out[e1] = 1.0f / (1.0f + __expf(-acc1));
    }
}

extern "C" void kernel_launch(void* const* d_in, const int* in_sizes, int n_in,
                              void* d_out, int out_size)
{
    const float* h   = (const float*)d_in[0];
    const int*   src = (const int*)d_in[1];
    const int*   dst = (const int*)d_in[2];
    float*       out = (float*)d_out;

    int E = in_sizes[1];  // number of edges

    long long groups = ((long long)E + 1) / 2;
    long long total_threads = groups * 8;
    int threads = 256;
    int blocks  = (int)((total_threads + threads - 1) / threads);

    dotpred_kernel<<<blocks, threads>>>(h, src, dst, out, E);
}